// round 5
// baseline (speedup 1.0000x reference)
#include <cuda_runtime.h>
#include <cstdint>

#define TT 2176

typedef unsigned int u32;

// ---------------- device scratch ----------------
__device__ float g_Q[8 * 16 * 128 * 128];      // (B,H,128,128) pre-scaled Q
__device__ float g_attn[8 * 128 * 2048];       // (B,T_NEW,C) attention output

extern __shared__ float sm[];

// ---------------- helpers ----------------
__device__ __forceinline__ u32 cvt_tf32(float f) {
    u32 r; asm("cvt.rna.tf32.f32 %0, %1;" : "=r"(r) : "f"(f)); return r;
}
__device__ __forceinline__ u32 smem_u32(const void* p) {
    return (u32)__cvta_generic_to_shared(p);
}
__device__ __forceinline__ void ldsm_x4(u32 a, u32& r0, u32& r1, u32& r2, u32& r3) {
    asm volatile("ldmatrix.sync.aligned.m8n8.x4.shared.b16 {%0,%1,%2,%3}, [%4];"
                 : "=r"(r0), "=r"(r1), "=r"(r2), "=r"(r3) : "r"(a));
}
__device__ __forceinline__ void mma8(float c[4], const u32 a[4], u32 b0, u32 b1) {
    asm volatile("mma.sync.aligned.m16n8k8.row.col.f32.tf32.tf32.f32 "
                 "{%0,%1,%2,%3}, {%4,%5,%6,%7}, {%8,%9}, {%0,%1,%2,%3};"
                 : "+f"(c[0]), "+f"(c[1]), "+f"(c[2]), "+f"(c[3])
                 : "r"(a[0]), "r"(a[1]), "r"(a[2]), "r"(a[3]), "r"(b0), "r"(b1));
}

// ---------------- pipelined tf32 GEMM core: 128x128 tile, BK=32, 2-stage ----------------
__device__ __forceinline__ void sts_tile(const float4 aL[4], const float4 bL[4],
                                         float* As, float* Bs,
                                         int ar, int ac, int br, int bc) {
#pragma unroll
    for (int j = 0; j < 4; j++) {
        uint4 ua = make_uint4(cvt_tf32(aL[j].x), cvt_tf32(aL[j].y),
                              cvt_tf32(aL[j].z), cvt_tf32(aL[j].w));
        *(uint4*)(As + (ar + 32 * j) * 36 + ac) = ua;
        uint4 ub = make_uint4(cvt_tf32(bL[j].x), cvt_tf32(bL[j].y),
                              cvt_tf32(bL[j].z), cvt_tf32(bL[j].w));
        *(uint4*)(Bs + (br + 8 * j) * 132 + bc) = ub;
    }
}

__device__ __forceinline__ void gemm_core(const float* __restrict__ A, const float* __restrict__ W,
                                          int m0, int n0, float c[4][4][4],
                                          float* As0, float* Bs0) {
    const int t = threadIdx.x, lane = t & 31, wid = t >> 5;
    const int ar = t >> 3, ac = (t & 7) * 4;
    const int br = t >> 5, bc = (t & 31) * 4;
    const int wm = (wid >> 2) * 64, wn = (wid & 3) * 32;
    const int g = lane & 3, nrow = lane >> 2;
    const u32 aoff = (((lane & 7) + ((lane >> 3) & 1) * 8) * 36 + (lane >> 4) * 4) * 4;

    const float* Ap = A + (size_t)(m0 + ar) * 2048 + ac;
    const float* Wp = W + (size_t)br * 2048 + n0 + bc;

    // prologue: load + store k0=0 into buffer 0
    {
        float4 aL[4], bL[4];
#pragma unroll
        for (int j = 0; j < 4; j++) aL[j] = *(const float4*)(Ap + (size_t)(32 * j) * 2048);
#pragma unroll
        for (int j = 0; j < 4; j++) bL[j] = *(const float4*)(Wp + (size_t)(8 * j) * 2048);
        sts_tile(aL, bL, As0, Bs0, ar, ac, br, bc);
    }

    int cur = 0;
    for (int k0 = 0; k0 < 2048; k0 += 32) {
        const bool more = (k0 + 32) < 2048;
        float4 aN[4], bN[4];
        if (more) {
#pragma unroll
            for (int j = 0; j < 4; j++)
                aN[j] = *(const float4*)(Ap + (size_t)(32 * j) * 2048 + k0 + 32);
#pragma unroll
            for (int j = 0; j < 4; j++)
                bN[j] = *(const float4*)(Wp + (size_t)(k0 + 32 + 8 * j) * 2048);
        }
        __syncthreads();
        float* As = As0 + cur * 4608;
        float* Bs = Bs0 + cur * 4224;
        const u32 abase = smem_u32(As) + aoff;
#pragma unroll
        for (int ks = 0; ks < 4; ks++) {
            u32 af[4][4];
#pragma unroll
            for (int mt = 0; mt < 4; mt++)
                ldsm_x4(abase + ((wm + mt * 16) * 36 + ks * 8) * 4,
                        af[mt][0], af[mt][1], af[mt][2], af[mt][3]);
            u32 bf[4][2];
#pragma unroll
            for (int nt = 0; nt < 4; nt++) {
                bf[nt][0] = __float_as_uint(Bs[(ks * 8 + g) * 132 + wn + nt * 8 + nrow]);
                bf[nt][1] = __float_as_uint(Bs[(ks * 8 + 4 + g) * 132 + wn + nt * 8 + nrow]);
            }
#pragma unroll
            for (int mt = 0; mt < 4; mt++)
#pragma unroll
                for (int nt = 0; nt < 4; nt++)
                    mma8(c[mt][nt], af[mt], bf[nt][0], bf[nt][1]);
        }
        if (more)
            sts_tile(aN, bN, As0 + (cur ^ 1) * 4608, Bs0 + (cur ^ 1) * 4224, ar, ac, br, bc);
        cur ^= 1;
    }
}

// ---------------- 1) fused QKV projection (pure GEMM) ----------------
__global__ __launch_bounds__(256) void qkv_kernel(
    const float* __restrict__ x,
    const float* __restrict__ Wq, const float* __restrict__ bq,
    const float* __restrict__ Wk, const float* __restrict__ bk,
    const float* __restrict__ Wv, const float* __restrict__ bv,
    float* __restrict__ Kout, float* __restrict__ Vout) {
    float* As0 = sm;
    float* Bs0 = sm + 2 * 4608;
    const int wsel = blockIdx.z;
    const float* W    = (wsel == 0) ? Wq : (wsel == 1 ? Wk : Wv);
    const float* bias = (wsel == 0) ? bq : (wsel == 1 ? bk : bv);
    const int m0 = blockIdx.y * 128, n0 = blockIdx.x * 128;

    float c[4][4][4];
#pragma unroll
    for (int i = 0; i < 4; i++)
#pragma unroll
        for (int j = 0; j < 4; j++)
#pragma unroll
            for (int k = 0; k < 4; k++) c[i][j][k] = 0.f;

    gemm_core(x, W, m0, n0, c, As0, Bs0);

    const int t = threadIdx.x, lane = t & 31, wid = t >> 5;
    const int wm = (wid >> 2) * 64, wn = (wid & 3) * 32;
    const int g = lane & 3, rq = lane >> 2;
    const float scale = (wsel == 0) ? 0.08838834764831845f : 1.0f;

#pragma unroll
    for (int mt = 0; mt < 4; mt++) {
#pragma unroll
        for (int nt = 0; nt < 4; nt++) {
            const int col = n0 + wn + nt * 8 + 2 * g;
            float2 bb = *(const float2*)(bias + col);
            const int h = col >> 7, dc = col & 127;
            const int row0 = m0 + wm + mt * 16 + rq;
#pragma unroll
            for (int half = 0; half < 2; half++) {
                const int gr = row0 + half * 8;
                const int b = gr >> 7, tq = gr & 127;
                float2 v;
                v.x = (c[mt][nt][half * 2 + 0] + bb.x) * scale;
                v.y = (c[mt][nt][half * 2 + 1] + bb.y) * scale;
                float* dst;
                if (wsel == 0) {
                    dst = g_Q + ((size_t)((b * 16 + h) * 128 + tq)) * 128 + dc;
                } else {
                    float* base = (wsel == 1) ? Kout : Vout;
                    dst = base + ((size_t)(b * 16 + h) * TT + 2048 + tq) * 128 + dc;
                }
                *(float2*)dst = v;
            }
        }
    }
}

// ---------------- 2) flash attention + KV-cache copy-through ----------------
// Reads K_past/V_past from inputs (tiles 0..15) and the new tail from the cache
// (tile 16, written by qkv). While loading each past tile it stores the raw
// float4s to the output cache — the copy-through costs only STG issue.
__global__ __launch_bounds__(256, 1) void attn_kernel(const float* __restrict__ Kpast,
                                                      const float* __restrict__ Vpast,
                                                      float* __restrict__ Kout,
                                                      float* __restrict__ Vout) {
    float* Qs = sm;                    // [q 128][d 132] tf32 bits
    float* Ks = Qs + 128 * 132;        // [key 128][d 132]
    float* Vs = Ks + 128 * 132;        // [d 128][key 132] (transposed)

    const int bh = blockIdx.x;
    const int t = threadIdx.x, lane = t & 31, wid = t >> 5;
    const int g = lane & 3, rq = lane >> 2;
    const int q0 = wid * 16;
    const int qlow = q0 + rq;

    // load Q (pre-scaled fp32) -> tf32 smem
    const float* Qg = g_Q + (size_t)bh * 128 * 128;
#pragma unroll
    for (int s = 0; s < 16; s++) {
        int i = t + s * 256;
        int r = i >> 5, c4 = (i & 31) * 4;
        float4 v = *(const float4*)(Qg + r * 128 + c4);
        uint4 u = make_uint4(cvt_tf32(v.x), cvt_tf32(v.y), cvt_tf32(v.z), cvt_tf32(v.w));
        *(uint4*)(Qs + r * 132 + c4) = u;
    }

    float m0r = -1e30f, m1r = -1e30f, l0r = 0.f, l1r = 0.f;
    float o[16][4];
#pragma unroll
    for (int i = 0; i < 16; i++)
#pragma unroll
        for (int j = 0; j < 4; j++) o[i][j] = 0.f;

    const float* KpB = Kpast + (size_t)bh * 2048 * 128;
    const float* VpB = Vpast + (size_t)bh * 2048 * 128;
    const float* KnB = Kout + ((size_t)bh * TT + 2048) * 128;
    const float* VnB = Vout + ((size_t)bh * TT + 2048) * 128;
    float* KoB = Kout + (size_t)bh * TT * 128;
    float* VoB = Vout + (size_t)bh * TT * 128;

    const u32 lfrag = (((lane & 7) * 132) + ((lane >> 3) & 1) * 4) * 4;
    const u32 pair8 = ((lane >> 4) & 1) * (8 * 132 * 4);   // +8 rows for ldsm_x4 pairing
    const u32 qbase = smem_u32(Qs) +
        (((q0 + (lane & 7) + ((lane >> 3) & 1) * 8) * 132) + (lane >> 4) * 4) * 4;
    const u32 kbase4 = smem_u32(Ks) + lfrag + pair8;
    const u32 vbase4 = smem_u32(Vs) + lfrag + pair8;

    for (int kt = 0; kt < 17; kt++) {
        const bool past = (kt < 16);
        const float* ksrc = past ? (KpB + (size_t)kt * 128 * 128) : KnB;
        const float* vsrc = past ? (VpB + (size_t)kt * 128 * 128) : VnB;
        float* kdst = KoB + (size_t)kt * 128 * 128;
        float* vdst = VoB + (size_t)kt * 128 * 128;
        __syncthreads();
        // K tile natural [key][d]; coalesced store-through of the raw data
#pragma unroll
        for (int s = 0; s < 16; s++) {
            int i = t + s * 256;
            int r = i >> 5, c4 = (i & 31) * 4;
            float4 v = *(const float4*)(ksrc + (size_t)r * 128 + c4);
            if (past) *(float4*)(kdst + (size_t)r * 128 + c4) = v;
            uint4 u = make_uint4(cvt_tf32(v.x), cvt_tf32(v.y), cvt_tf32(v.z), cvt_tf32(v.w));
            *(uint4*)(Ks + r * 132 + c4) = u;
        }
        // V tile transposed [d][key]; store-through raw
#pragma unroll
        for (int s = 0; s < 16; s++) {
            int r = lane + (s & 3) * 32;
            int c4 = (wid + (s >> 2) * 8) * 4;
            float4 v = *(const float4*)(vsrc + (size_t)r * 128 + c4);
            if (past) *(float4*)(vdst + (size_t)r * 128 + c4) = v;
            Vs[(c4 + 0) * 132 + r] = __uint_as_float(cvt_tf32(v.x));
            Vs[(c4 + 1) * 132 + r] = __uint_as_float(cvt_tf32(v.y));
            Vs[(c4 + 2) * 132 + r] = __uint_as_float(cvt_tf32(v.z));
            Vs[(c4 + 3) * 132 + r] = __uint_as_float(cvt_tf32(v.w));
        }
        __syncthreads();

        // ---- S = Q @ K^T (ldsm_x4 serves two jt tiles per issue) ----
        float s_[16][4];
#pragma unroll
        for (int i = 0; i < 16; i++)
#pragma unroll
            for (int j = 0; j < 4; j++) s_[i][j] = 0.f;

#pragma unroll
        for (int ks = 0; ks < 16; ks++) {
            u32 af[4];
            ldsm_x4(qbase + ks * 32, af[0], af[1], af[2], af[3]);
#pragma unroll
            for (int jt = 0; jt < 16; jt += 2) {
                u32 b0, b1, b2, b3;
                ldsm_x4(kbase4 + jt * 4224 + ks * 32, b0, b1, b2, b3);
                mma8(s_[jt],     af, b0, b1);
                mma8(s_[jt + 1], af, b2, b3);
            }
        }

        // ---- causal mask (last tile only) ----
        if (kt == 16) {
#pragma unroll
            for (int jt = 0; jt < 16; jt++) {
                int kk = jt * 8 + 2 * g;
                if (kk     > qlow)     s_[jt][0] = -1e30f;
                if (kk + 1 > qlow)     s_[jt][1] = -1e30f;
                if (kk     > qlow + 8) s_[jt][2] = -1e30f;
                if (kk + 1 > qlow + 8) s_[jt][3] = -1e30f;
            }
        }

        // ---- online softmax (register state) ----
        float mx0 = -1e30f, mx1 = -1e30f;
#pragma unroll
        for (int jt = 0; jt < 16; jt++) {
            mx0 = fmaxf(mx0, fmaxf(s_[jt][0], s_[jt][1]));
            mx1 = fmaxf(mx1, fmaxf(s_[jt][2], s_[jt][3]));
        }
        mx0 = fmaxf(mx0, __shfl_xor_sync(0xffffffffu, mx0, 1));
        mx0 = fmaxf(mx0, __shfl_xor_sync(0xffffffffu, mx0, 2));
        mx1 = fmaxf(mx1, __shfl_xor_sync(0xffffffffu, mx1, 1));
        mx1 = fmaxf(mx1, __shfl_xor_sync(0xffffffffu, mx1, 2));
        float mn0 = fmaxf(m0r, mx0), mn1 = fmaxf(m1r, mx1);
        float f0 = __expf(m0r - mn0), f1 = __expf(m1r - mn1);
        m0r = mn0; m1r = mn1;

        float ps0 = 0.f, ps1 = 0.f;
#pragma unroll
        for (int jt = 0; jt < 16; jt++) {
            float p0 = __expf(s_[jt][0] - m0r);
            float p1 = __expf(s_[jt][1] - m0r);
            float p2 = __expf(s_[jt][2] - m1r);
            float p3 = __expf(s_[jt][3] - m1r);
            s_[jt][0] = p0; s_[jt][1] = p1; s_[jt][2] = p2; s_[jt][3] = p3;
            ps0 += p0 + p1; ps1 += p2 + p3;
        }
        ps0 += __shfl_xor_sync(0xffffffffu, ps0, 1);
        ps0 += __shfl_xor_sync(0xffffffffu, ps0, 2);
        ps1 += __shfl_xor_sync(0xffffffffu, ps1, 1);
        ps1 += __shfl_xor_sync(0xffffffffu, ps1, 2);
        l0r = l0r * f0 + ps0;
        l1r = l1r * f1 + ps1;

#pragma unroll
        for (int dn = 0; dn < 16; dn++) {
            o[dn][0] *= f0; o[dn][1] *= f0;
            o[dn][2] *= f1; o[dn][3] *= f1;
        }

        // ---- O += P @ V : shfl-permute S-accum -> A-frag; x4 serves two dn ----
        const int src0 = (lane & ~3) | (g >> 1);
        const int src1 = src0 + 2;
#pragma unroll
        for (int jt = 0; jt < 16; jt++) {
            float t00 = __shfl_sync(0xffffffffu, s_[jt][0], src0);
            float t01 = __shfl_sync(0xffffffffu, s_[jt][1], src0);
            float t10 = __shfl_sync(0xffffffffu, s_[jt][0], src1);
            float t11 = __shfl_sync(0xffffffffu, s_[jt][1], src1);
            float t20 = __shfl_sync(0xffffffffu, s_[jt][2], src0);
            float t21 = __shfl_sync(0xffffffffu, s_[jt][3], src0);
            float t30 = __shfl_sync(0xffffffffu, s_[jt][2], src1);
            float t31 = __shfl_sync(0xffffffffu, s_[jt][3], src1);
            u32 pa[4];
            pa[0] = cvt_tf32((g & 1) ? t01 : t00);
            pa[1] = cvt_tf32((g & 1) ? t21 : t20);
            pa[2] = cvt_tf32((g & 1) ? t11 : t10);
            pa[3] = cvt_tf32((g & 1) ? t31 : t30);
#pragma unroll
            for (int dn = 0; dn < 16; dn += 2) {
                u32 b0, b1, b2, b3;
                ldsm_x4(vbase4 + dn * 4224 + jt * 32, b0, b1, b2, b3);
                mma8(o[dn],     pa, b0, b1);
                mma8(o[dn + 1], pa, b2, b3);
            }
        }
    }

    // ---- epilogue ----
    const float inv0 = 1.f / l0r, inv1 = 1.f / l1r;
    const int b = bh >> 4, h = bh & 15;
    float* outp = g_attn + ((size_t)(b * 128 + qlow)) * 2048 + h * 128;
#pragma unroll
    for (int dn = 0; dn < 16; dn++) {
        const int col = dn * 8 + 2 * g;
        float2 v0 = make_float2(o[dn][0] * inv0, o[dn][1] * inv0);
        float2 v1 = make_float2(o[dn][2] * inv1, o[dn][3] * inv1);
        *(float2*)(outp + col) = v0;
        *(float2*)(outp + (size_t)8 * 2048 + col) = v1;
    }
}

// ---------------- 3) output projection ----------------
__global__ __launch_bounds__(256) void proj_kernel(const float* __restrict__ Wo,
                                                   const float* __restrict__ bo,
                                                   float* __restrict__ out) {
    float* As0 = sm;
    float* Bs0 = sm + 2 * 4608;
    const int m0 = blockIdx.y * 128, n0 = blockIdx.x * 128;

    float c[4][4][4];
#pragma unroll
    for (int i = 0; i < 4; i++)
#pragma unroll
        for (int j = 0; j < 4; j++)
#pragma unroll
            for (int k = 0; k < 4; k++) c[i][j][k] = 0.f;

    gemm_core(g_attn, Wo, m0, n0, c, As0, Bs0);

    const int t = threadIdx.x, lane = t & 31, wid = t >> 5;
    const int wm = (wid >> 2) * 64, wn = (wid & 3) * 32;
    const int g = lane & 3, rq = lane >> 2;

#pragma unroll
    for (int mt = 0; mt < 4; mt++) {
#pragma unroll
        for (int nt = 0; nt < 4; nt++) {
            const int col = n0 + wn + nt * 8 + 2 * g;
            float2 bb = *(const float2*)(bo + col);
            const int row0 = m0 + wm + mt * 16 + rq;
            float2 v0 = make_float2(c[mt][nt][0] + bb.x, c[mt][nt][1] + bb.y);
            float2 v1 = make_float2(c[mt][nt][2] + bb.x, c[mt][nt][3] + bb.y);
            *(float2*)(out + (size_t)row0 * 2048 + col) = v0;
            *(float2*)(out + (size_t)(row0 + 8) * 2048 + col) = v1;
        }
    }
}

// ---------------- launch ----------------
extern "C" void kernel_launch(void* const* d_in, const int* in_sizes, int n_in,
                              void* d_out, int out_size) {
    const float* x  = (const float*)d_in[0];
    const float* Kp = (const float*)d_in[1];
    const float* Vp = (const float*)d_in[2];
    const float* Wq = (const float*)d_in[3];
    const float* bq = (const float*)d_in[4];
    const float* Wk = (const float*)d_in[5];
    const float* bk = (const float*)d_in[6];
    const float* Wv = (const float*)d_in[7];
    const float* bv = (const float*)d_in[8];
    const float* Wo = (const float*)d_in[9];
    const float* bo = (const float*)d_in[10];

    float* out  = (float*)d_out;
    float* Kout = (float*)d_out + 2097152;                 // B*T_NEW*C
    float* Vout = (float*)d_out + 2097152 + 35651584;      // + B*H*TT*D

    const int gemm_smem = (2 * 4608 + 2 * 4224) * (int)sizeof(float);   // 70656 B
    cudaFuncSetAttribute(qkv_kernel, cudaFuncAttributeMaxDynamicSharedMemorySize, gemm_smem);
    cudaFuncSetAttribute(proj_kernel, cudaFuncAttributeMaxDynamicSharedMemorySize, gemm_smem);

    // 1) QKV projection (writes g_Q + new cache tail)
    qkv_kernel<<<dim3(16, 8, 3), 256, gemm_smem>>>(x, Wq, bq, Wk, bk, Wv, bv, Kout, Vout);

    // 2) attention + KV copy-through (past from inputs, new tail from cache)
    const int attn_smem = 3 * 128 * 132 * (int)sizeof(float);   // 202752 B
    cudaFuncSetAttribute(attn_kernel, cudaFuncAttributeMaxDynamicSharedMemorySize, attn_smem);
    attn_kernel<<<128, 256, attn_smem>>>(Kp, Vp, Kout, Vout);

    // 3) output projection
    proj_kernel<<<dim3(16, 8), 256, gemm_smem>>>(Wo, bo, out);
}